// round 13
// baseline (speedup 1.0000x reference)
#include <cuda_runtime.h>
#include <cuda_bf16.h>

#define BATCH 4096
#define TLEN  2048
#define DIN   5
#define H1    9
#define H2    32
#define OUTL  25

// 2*log2(e): folded into stage-1/2 weights so tanh needs no pre-multiply.
#define C2L2E 2.8853900817779268f

// Scratch for stage-1 result y = [h_f | h_b] per batch row.
__device__ float g_y[BATCH * 2 * H1];

// ---------------------------------------------------------------------------
// Stage 1: bidirectional Elman RNN over T=2048. THREAD-per-sequence (no
// sync/SHFL/LDS on the serial path), software-pipelined within each step:
//   block 1: recurrent matvec za/zb chains from precomputed zin (needs r)
//   block 2: zin for step t+1 from x (independent of r -> fills latency)
//   block 3: tanh (ex2 + rcp)
// State kept as r = rcp(exp(z')+1); h = 1-2r folded into recurrent weights
// and bias. x streamed in 4-step chunks of 5 x float4, double-buffered.
// ---------------------------------------------------------------------------
__global__ __launch_bounds__(128, 1) void rnn1_kernel(
    const float* __restrict__ x,
    const float* __restrict__ w_ih_f, const float* __restrict__ w_hh_f,
    const float* __restrict__ b_ih_f, const float* __restrict__ b_hh_f,
    const float* __restrict__ w_ih_b, const float* __restrict__ w_hh_b,
    const float* __restrict__ b_ih_b, const float* __restrict__ b_hh_b)
{
    const int tid = blockIdx.x * 128 + threadIdx.x;   // 0..8191
    const int dir = tid >> 12;                        // block-uniform (4096/128=32)
    const int b   = tid & (BATCH - 1);

    const float* wih_g = dir ? w_ih_b : w_ih_f;
    const float* whh_g = dir ? w_hh_b : w_hh_f;
    const float* bi_g  = dir ? b_ih_b : b_ih_f;
    const float* bh_g  = dir ? b_hh_b : b_hh_f;

    // Per-thread weight registers (scaled / folded).
    float wih[H1 * DIN];        // C2L2E * w_ih[j][d]
    float whh2[H1 * H1];        // -2*C2L2E * w_hh[j][k]
    float bz[H1];               // C2L2E * (b_ih + b_hh + sum_k w_hh[j][k])
    float r[H1];
    float zinA[H1], zinB[H1];   // input-part accumulators, ping-pong
#pragma unroll
    for (int j = 0; j < H1; j++) {
#pragma unroll
        for (int d = 0; d < DIN; d++)
            wih[j * DIN + d] = C2L2E * __ldg(wih_g + j * DIN + d);
        float wsum = 0.0f;
#pragma unroll
        for (int k = 0; k < H1; k++) {
            float w = __ldg(whh_g + j * H1 + k);
            wsum += w;
            whh2[j * H1 + k] = -2.0f * C2L2E * w;
        }
        bz[j] = C2L2E * (__ldg(bi_g + j) + __ldg(bh_g + j) + wsum);
        r[j] = 0.5f;            // h = 1-2r = 0
    }

    const float4* xq = reinterpret_cast<const float4*>(x + (size_t)b * (TLEN * DIN));
    const int q0  = dir ? (TLEN / 4 - 1) * DIN : 0;   // 2555 or 0
    const int qdq = dir ? -DIN : DIN;                 // +-5 float4 per 4-step chunk

#define LOADCHUNK(c, R) do {                                   \
        const float4* _p = xq + (q0 + (c) * qdq);              \
        R[0] = __ldg(_p + 0); R[1] = __ldg(_p + 1);            \
        R[2] = __ldg(_p + 2); R[3] = __ldg(_p + 3);            \
        R[4] = __ldg(_p + 4);                                  \
    } while (0)

    // Compute input-part for a step: Z[j] = bz[j] + sum_d wih[j][d]*x_d
#define ZIN(Z, x0, x1, x2, x3, x4) do {                                    \
        _Pragma("unroll")                                                  \
        for (int j = 0; j < H1; j++) {                                     \
            float t = fmaf(wih[j * DIN + 0], (x0), bz[j]);                 \
            t = fmaf(wih[j * DIN + 1], (x1), t);                           \
            t = fmaf(wih[j * DIN + 2], (x2), t);                           \
            t = fmaf(wih[j * DIN + 3], (x3), t);                           \
            t = fmaf(wih[j * DIN + 4], (x4), t);                           \
            Z[j] = t;                                                      \
        }                                                                  \
    } while (0)

    // One step: recurrence from ZC, then prepare ZN for next step (fills
    // latency windows), then tanh.
#define STEP(ZC, ZN, x0, x1, x2, x3, x4) do {                              \
        float s_[H1];                                                      \
        _Pragma("unroll")                                                  \
        for (int j = 0; j < H1; j++) {                                     \
            float za = fmaf(whh2[j * H1 + 0], r[0], ZC[j]);                \
            float zb = whh2[j * H1 + 1] * r[1];                            \
            za = fmaf(whh2[j * H1 + 2], r[2], za);                         \
            zb = fmaf(whh2[j * H1 + 3], r[3], zb);                         \
            za = fmaf(whh2[j * H1 + 4], r[4], za);                         \
            zb = fmaf(whh2[j * H1 + 5], r[5], zb);                         \
            za = fmaf(whh2[j * H1 + 6], r[6], za);                         \
            zb = fmaf(whh2[j * H1 + 7], r[7], zb);                         \
            za = fmaf(whh2[j * H1 + 8], r[8], za);                         \
            s_[j] = za + zb;                                               \
        }                                                                  \
        ZIN(ZN, x0, x1, x2, x3, x4);                                       \
        _Pragma("unroll")                                                  \
        for (int j = 0; j < H1; j++) {                                     \
            float e;                                                       \
            asm("ex2.approx.f32 %0, %1;" : "=f"(e) : "f"(s_[j]));          \
            asm("rcp.approx.f32 %0, %1;" : "=f"(r[j]) : "f"(e + 1.0f));    \
        }                                                                  \
    } while (0)

    // Chunk = 4 steps. Step t's x lives at floats [5t..5t+4] of the 20-float
    // chunk. Each STEP consumes zin for its own step and prepares the NEXT
    // step's zin, so the last STEP needs the next chunk's first-step x (RN).
#define CHUNK_FWD(R, RN)                                                   \
        STEP(zinA, zinB, R[1].y, R[1].z, R[1].w, R[2].x, R[2].y);          \
        STEP(zinB, zinA, R[2].z, R[2].w, R[3].x, R[3].y, R[3].z);          \
        STEP(zinA, zinB, R[3].w, R[4].x, R[4].y, R[4].z, R[4].w);          \
        STEP(zinB, zinA, RN[0].x, RN[0].y, RN[0].z, RN[0].w, RN[1].x);

#define CHUNK_BWD(R, RN)                                                   \
        STEP(zinA, zinB, R[2].z, R[2].w, R[3].x, R[3].y, R[3].z);          \
        STEP(zinB, zinA, R[1].y, R[1].z, R[1].w, R[2].x, R[2].y);          \
        STEP(zinA, zinB, R[0].x, R[0].y, R[0].z, R[0].w, R[1].x);          \
        STEP(zinB, zinA, RN[3].w, RN[4].x, RN[4].y, RN[4].z, RN[4].w);

    float4 A[5], B[5];
    LOADCHUNK(0, A);
    // Prime zinA with the true first step's input part.
    if (dir == 0) ZIN(zinA, A[0].x, A[0].y, A[0].z, A[0].w, A[1].x);
    else          ZIN(zinA, A[3].w, A[4].x, A[4].y, A[4].z, A[4].w);

    const int NCHUNK = TLEN / 4;   // 512 (even)
    if (dir == 0) {
        for (int c = 0; c < NCHUNK; c += 2) {
            LOADCHUNK(c + 1, B);
            CHUNK_FWD(A, B);
            if (c + 2 < NCHUNK) LOADCHUNK(c + 2, A);
            CHUNK_FWD(B, A);   // last iter: A holds stale data; the zin it
                               // produces is for step 2048 and never consumed
        }
    } else {
        for (int c = 0; c < NCHUNK; c += 2) {
            LOADCHUNK(c + 1, B);
            CHUNK_BWD(A, B);
            if (c + 2 < NCHUNK) LOADCHUNK(c + 2, A);
            CHUNK_BWD(B, A);
        }
    }

    float* yo = g_y + b * (2 * H1) + dir * H1;
#pragma unroll
    for (int j = 0; j < H1; j++) yo[j] = fmaf(-2.0f, r[j], 1.0f);
#undef LOADCHUNK
#undef ZIN
#undef STEP
#undef CHUNK_FWD
#undef CHUNK_BWD
}

// ---------------------------------------------------------------------------
// Stage 2: 25-step RNN (input only at t=0) + linear 32->3.  (Proven R5 logic;
// weight prologue vectorized to float4 loads.)
// ---------------------------------------------------------------------------
__global__ __launch_bounds__(256) void rnn2_kernel(
    const float* __restrict__ w_ih2, const float* __restrict__ w_hh2,
    const float* __restrict__ b_ih2, const float* __restrict__ b_hh2,
    const float* __restrict__ w_out, const float* __restrict__ b_out,
    float* __restrict__ out)
{
    __shared__ __align__(16) float rbuf[8][2][H2];   // [warp][parity][32]

    const int gtid = blockIdx.x * blockDim.x + threadIdx.x;
    const int b  = gtid >> 5;
    const int j  = gtid & 31;
    const int wl = (threadIdx.x >> 5);

    // Recurrent weights via vector loads (rows are 128B-aligned).
    float wh2[H2];
    float wsum = 0.0f;
    {
        const float4* wrow = reinterpret_cast<const float4*>(w_hh2 + j * H2);
#pragma unroll
        for (int q = 0; q < H2 / 4; q++) {
            const float4 v = __ldg(wrow + q);
            wsum += (v.x + v.y) + (v.z + v.w);
            wh2[4 * q + 0] = -2.0f * C2L2E * v.x;
            wh2[4 * q + 1] = -2.0f * C2L2E * v.y;
            wh2[4 * q + 2] = -2.0f * C2L2E * v.z;
            wh2[4 * q + 3] = -2.0f * C2L2E * v.w;
        }
    }
    const float bin = C2L2E * (__ldg(b_ih2 + j) + __ldg(b_hh2 + j));
    const float bz  = bin + C2L2E * wsum;

    const int oc = (j < 3) ? j : 0;
    float wor[H2];
    float osum = 0.0f;
    {
        const float4* orow = reinterpret_cast<const float4*>(w_out + oc * H2);
#pragma unroll
        for (int q = 0; q < H2 / 4; q++) {
            const float4 v = __ldg(orow + q);
            osum += (v.x + v.y) + (v.z + v.w);
            wor[4 * q + 0] = -2.0f * v.x;
            wor[4 * q + 1] = -2.0f * v.y;
            wor[4 * q + 2] = -2.0f * v.z;
            wor[4 * q + 3] = -2.0f * v.w;
        }
    }
    const float oconst = osum + __ldg(b_out + oc);

    float* sb = &rbuf[wl][0][0];                 // parity stride = 32 floats

    // ---- Step 0: h = tanh(W_ih2 @ y + b). Broadcast y via smem.
    sb[j] = (j < 2 * H1) ? g_y[b * (2 * H1) + j] : 0.0f;
    __syncwarp();
    float r;
    {
        const float4 y0 = *reinterpret_cast<const float4*>(sb + 0);
        const float4 y1 = *reinterpret_cast<const float4*>(sb + 4);
        const float4 y2 = *reinterpret_cast<const float4*>(sb + 8);
        const float4 y3 = *reinterpret_cast<const float4*>(sb + 12);
        const float  y16 = sb[16], y17 = sb[17];
        float za = bin, zb = 0.0f;
        const float* wi = w_ih2 + j * (2 * H1);
        za = fmaf(C2L2E * __ldg(wi + 0),  y0.x, za);
        zb = fmaf(C2L2E * __ldg(wi + 1),  y0.y, zb);
        za = fmaf(C2L2E * __ldg(wi + 2),  y0.z, za);
        zb = fmaf(C2L2E * __ldg(wi + 3),  y0.w, zb);
        za = fmaf(C2L2E * __ldg(wi + 4),  y1.x, za);
        zb = fmaf(C2L2E * __ldg(wi + 5),  y1.y, zb);
        za = fmaf(C2L2E * __ldg(wi + 6),  y1.z, za);
        zb = fmaf(C2L2E * __ldg(wi + 7),  y1.w, zb);
        za = fmaf(C2L2E * __ldg(wi + 8),  y2.x, za);
        zb = fmaf(C2L2E * __ldg(wi + 9),  y2.y, zb);
        za = fmaf(C2L2E * __ldg(wi + 10), y2.z, za);
        zb = fmaf(C2L2E * __ldg(wi + 11), y2.w, zb);
        za = fmaf(C2L2E * __ldg(wi + 12), y3.x, za);
        zb = fmaf(C2L2E * __ldg(wi + 13), y3.y, zb);
        za = fmaf(C2L2E * __ldg(wi + 14), y3.z, za);
        zb = fmaf(C2L2E * __ldg(wi + 15), y3.w, zb);
        za = fmaf(C2L2E * __ldg(wi + 16), y16, za);
        zb = fmaf(C2L2E * __ldg(wi + 17), y17, zb);
        float e;
        asm("ex2.approx.f32 %0, %1;" : "=f"(e) : "f"(za + zb));
        asm("rcp.approx.f32 %0, %1;" : "=f"(r) : "f"(e + 1.0f));
    }

    float* ob = out + (size_t)b * OUTL * 3;
    int p = 0;

    for (int t = 0; t < OUTL; t++) {
        sb[p * H2 + j] = r;
        __syncwarp();
        float rv[H2];
#pragma unroll
        for (int q = 0; q < H2; q += 4) {
            const float4 v = *reinterpret_cast<const float4*>(sb + p * H2 + q);
            rv[q] = v.x; rv[q + 1] = v.y; rv[q + 2] = v.z; rv[q + 3] = v.w;
        }

        float s0 = oconst, s1 = 0.f, s2 = 0.f, s3 = 0.f;
#pragma unroll
        for (int k = 0; k < H2; k += 4) {
            s0 = fmaf(wor[k],     rv[k],     s0);
            s1 = fmaf(wor[k + 1], rv[k + 1], s1);
            s2 = fmaf(wor[k + 2], rv[k + 2], s2);
            s3 = fmaf(wor[k + 3], rv[k + 3], s3);
        }
        if (j < 3) ob[t * 3 + j] = (s0 + s1) + (s2 + s3);

        if (t < OUTL - 1) {
            float q0 = bz, q1 = 0.f, q2 = 0.f, q3 = 0.f;
#pragma unroll
            for (int k = 0; k < H2; k += 4) {
                q0 = fmaf(wh2[k],     rv[k],     q0);
                q1 = fmaf(wh2[k + 1], rv[k + 1], q1);
                q2 = fmaf(wh2[k + 2], rv[k + 2], q2);
                q3 = fmaf(wh2[k + 3], rv[k + 3], q3);
            }
            float e;
            asm("ex2.approx.f32 %0, %1;" : "=f"(e) : "f"((q0 + q1) + (q2 + q3)));
            asm("rcp.approx.f32 %0, %1;" : "=f"(r) : "f"(e + 1.0f));
        }
        p ^= 1;
    }
}

extern "C" void kernel_launch(void* const* d_in, const int* in_sizes, int n_in,
                              void* d_out, int out_size)
{
    const float* x      = (const float*)d_in[0];
    const float* w_ih_f = (const float*)d_in[1];
    const float* w_hh_f = (const float*)d_in[2];
    const float* b_ih_f = (const float*)d_in[3];
    const float* b_hh_f = (const float*)d_in[4];
    const float* w_ih_b = (const float*)d_in[5];
    const float* w_hh_b = (const float*)d_in[6];
    const float* b_ih_b = (const float*)d_in[7];
    const float* b_hh_b = (const float*)d_in[8];
    const float* w_ih2  = (const float*)d_in[9];
    const float* w_hh2  = (const float*)d_in[10];
    const float* b_ih2  = (const float*)d_in[11];
    const float* b_hh2  = (const float*)d_in[12];
    const float* w_out  = (const float*)d_in[13];
    const float* b_out  = (const float*)d_in[14];
    float* out = (float*)d_out;

    // Stage 1: thread per sequence. 8192 threads = 64 blocks x 128.
    rnn1_kernel<<<(2 * BATCH) / 128, 128>>>(x, w_ih_f, w_hh_f, b_ih_f, b_hh_f,
                                            w_ih_b, w_hh_b, b_ih_b, b_hh_b);

    // Stage 2: warp per batch row.
    rnn2_kernel<<<(BATCH * 32) / 256, 256>>>(w_ih2, w_hh2, b_ih2, b_hh2,
                                             w_out, b_out, out);
}

// round 14
// speedup vs baseline: 1.4052x; 1.4052x over previous
#include <cuda_runtime.h>
#include <cuda_bf16.h>

#define BATCH 4096
#define TLEN  2048
#define DIN   5
#define H1    9
#define H2    32
#define OUTL  25

// 2*log2(e): folded into stage-1/2 weights so tanh needs no pre-multiply.
#define C2L2E 2.8853900817779268f

// Scratch for stage-1 result y = [h_f | h_b] per batch row.
__device__ float g_y[BATCH * 2 * H1];

#define FMA2(d, a, b, c) \
    asm("fma.rn.f32x2 %0, %1, %2, %3;" : "=l"(d) : "l"(a), "l"(b), "l"(c))
#define MUL2(d, a, b) \
    asm("mul.rn.f32x2 %0, %1, %2;" : "=l"(d) : "l"(a), "l"(b))
#define ADD2(d, a, b) \
    asm("add.rn.f32x2 %0, %1, %2;" : "=l"(d) : "l"(a), "l"(b))
#define PACK2(d, lo, hi) \
    asm("mov.b64 %0, {%1, %2};" : "=l"(d) : "r"(__float_as_uint(lo)), "r"(__float_as_uint(hi)))
#define UNPACK2(lo, hi, s) \
    asm("mov.b64 {%0, %1}, %2;" : "=r"(lo), "=r"(hi) : "l"(s))

// ---------------------------------------------------------------------------
// Stage 1: bidirectional Elman RNN over T=2048. THREAD-per-sequence (no
// sync/SHFL/LDS on the serial path). Neurons 0-7 packed as 4 f32x2 pairs
// (fma.rn.f32x2 halves the FMA-pipe slots), neuron 8 scalar. Weight register
// cost unchanged vs scalar (two distinct neurons per 64-bit pair).
// State r = rcp(exp(z')+1); h = 1-2r folded into recurrent weights and bias.
// x streamed in 4-step chunks of 5 x float4, double-buffered.
// ---------------------------------------------------------------------------
__global__ __launch_bounds__(128, 1) void rnn1_kernel(
    const float* __restrict__ x,
    const float* __restrict__ w_ih_f, const float* __restrict__ w_hh_f,
    const float* __restrict__ b_ih_f, const float* __restrict__ b_hh_f,
    const float* __restrict__ w_ih_b, const float* __restrict__ w_hh_b,
    const float* __restrict__ b_ih_b, const float* __restrict__ b_hh_b)
{
    const int tid = blockIdx.x * 128 + threadIdx.x;   // 0..8191
    const int dir = tid >> 12;                        // block-uniform (4096/128=32)
    const int b   = tid & (BATCH - 1);

    const float* wih_g = dir ? w_ih_b : w_ih_f;
    const float* whh_g = dir ? w_hh_b : w_hh_f;
    const float* bi_g  = dir ? b_ih_b : b_ih_f;
    const float* bh_g  = dir ? b_hh_b : b_hh_f;

    // Packed weights: pair p covers neurons (2p, 2p+1), p=0..3; neuron 8 scalar.
    unsigned long long wihP[4 * DIN];   // (C*w_ih[2p][d], C*w_ih[2p+1][d])
    unsigned long long whhP[4 * H1];    // (-2C*w_hh[2p][k], -2C*w_hh[2p+1][k])
    unsigned long long bzP[4];
    float wih8[DIN], whh8[H1], bz8;
    float r[H1];

#pragma unroll
    for (int p = 0; p < 4; p++) {
        const int j0 = 2 * p, j1 = 2 * p + 1;
#pragma unroll
        for (int d = 0; d < DIN; d++)
            PACK2(wihP[p * DIN + d], C2L2E * __ldg(wih_g + j0 * DIN + d),
                                     C2L2E * __ldg(wih_g + j1 * DIN + d));
        float ws0 = 0.0f, ws1 = 0.0f;
#pragma unroll
        for (int k = 0; k < H1; k++) {
            const float w0 = __ldg(whh_g + j0 * H1 + k);
            const float w1 = __ldg(whh_g + j1 * H1 + k);
            ws0 += w0; ws1 += w1;
            PACK2(whhP[p * H1 + k], -2.0f * C2L2E * w0, -2.0f * C2L2E * w1);
        }
        PACK2(bzP[p], C2L2E * (__ldg(bi_g + j0) + __ldg(bh_g + j0) + ws0),
                      C2L2E * (__ldg(bi_g + j1) + __ldg(bh_g + j1) + ws1));
    }
    {
        float ws = 0.0f;
#pragma unroll
        for (int d = 0; d < DIN; d++) wih8[d] = C2L2E * __ldg(wih_g + 8 * DIN + d);
#pragma unroll
        for (int k = 0; k < H1; k++) {
            const float w = __ldg(whh_g + 8 * H1 + k);
            ws += w;
            whh8[k] = -2.0f * C2L2E * w;
        }
        bz8 = C2L2E * (__ldg(bi_g + 8) + __ldg(bh_g + 8) + ws);
    }
#pragma unroll
    for (int j = 0; j < H1; j++) r[j] = 0.5f;     // h = 1-2r = 0

    const float4* xq = reinterpret_cast<const float4*>(x + (size_t)b * (TLEN * DIN));
    const int q0  = dir ? (TLEN / 4 - 1) * DIN : 0;   // 2555 or 0
    const int qdq = dir ? -DIN : DIN;                 // +-5 float4 per 4-step chunk

#define LOADCHUNK(c, R) do {                                   \
        const float4* _p = xq + (q0 + (c) * qdq);              \
        R[0] = __ldg(_p + 0); R[1] = __ldg(_p + 1);            \
        R[2] = __ldg(_p + 2); R[3] = __ldg(_p + 3);            \
        R[4] = __ldg(_p + 4);                                  \
    } while (0)

    // One RNN step: all reads of r[] precede the tanh writes.
#define STEP(x0, x1, x2, x3, x4) do {                                      \
        unsigned long long xx0, xx1, xx2, xx3, xx4;                        \
        PACK2(xx0, (x0), (x0)); PACK2(xx1, (x1), (x1));                    \
        PACK2(xx2, (x2), (x2)); PACK2(xx3, (x3), (x3));                    \
        PACK2(xx4, (x4), (x4));                                            \
        unsigned long long rr0, rr1, rr2, rr3, rr4, rr5, rr6, rr7, rr8;    \
        PACK2(rr0, r[0], r[0]); PACK2(rr1, r[1], r[1]);                    \
        PACK2(rr2, r[2], r[2]); PACK2(rr3, r[3], r[3]);                    \
        PACK2(rr4, r[4], r[4]); PACK2(rr5, r[5], r[5]);                    \
        PACK2(rr6, r[6], r[6]); PACK2(rr7, r[7], r[7]);                    \
        PACK2(rr8, r[8], r[8]);                                            \
        float zs[H1];                                                      \
        _Pragma("unroll")                                                  \
        for (int p = 0; p < 4; p++) {                                      \
            unsigned long long a0, a1;                                     \
            FMA2(a0, wihP[p * DIN + 0], xx0, bzP[p]);                      \
            MUL2(a1, wihP[p * DIN + 1], xx1);                              \
            FMA2(a0, wihP[p * DIN + 2], xx2, a0);                          \
            FMA2(a1, wihP[p * DIN + 3], xx3, a1);                          \
            FMA2(a0, wihP[p * DIN + 4], xx4, a0);                          \
            FMA2(a0, whhP[p * H1 + 0], rr0, a0);                           \
            FMA2(a1, whhP[p * H1 + 1], rr1, a1);                           \
            FMA2(a0, whhP[p * H1 + 2], rr2, a0);                           \
            FMA2(a1, whhP[p * H1 + 3], rr3, a1);                           \
            FMA2(a0, whhP[p * H1 + 4], rr4, a0);                           \
            FMA2(a1, whhP[p * H1 + 5], rr5, a1);                           \
            FMA2(a0, whhP[p * H1 + 6], rr6, a0);                           \
            FMA2(a1, whhP[p * H1 + 7], rr7, a1);                           \
            FMA2(a0, whhP[p * H1 + 8], rr8, a0);                           \
            ADD2(a0, a0, a1);                                              \
            unsigned lo_, hi_;                                             \
            UNPACK2(lo_, hi_, a0);                                         \
            zs[2 * p]     = __uint_as_float(lo_);                          \
            zs[2 * p + 1] = __uint_as_float(hi_);                          \
        }                                                                  \
        {                                                                  \
            float za = fmaf(wih8[0], (x0), bz8);                           \
            float zb = wih8[1] * (x1);                                     \
            za = fmaf(wih8[2], (x2), za);                                  \
            zb = fmaf(wih8[3], (x3), zb);                                  \
            za = fmaf(wih8[4], (x4), za);                                  \
            za = fmaf(whh8[0], r[0], za);                                  \
            zb = fmaf(whh8[1], r[1], zb);                                  \
            za = fmaf(whh8[2], r[2], za);                                  \
            zb = fmaf(whh8[3], r[3], zb);                                  \
            za = fmaf(whh8[4], r[4], za);                                  \
            zb = fmaf(whh8[5], r[5], zb);                                  \
            za = fmaf(whh8[6], r[6], za);                                  \
            zb = fmaf(whh8[7], r[7], zb);                                  \
            za = fmaf(whh8[8], r[8], za);                                  \
            zs[8] = za + zb;                                               \
        }                                                                  \
        _Pragma("unroll")                                                  \
        for (int j = 0; j < H1; j++) {                                     \
            float e;                                                       \
            asm("ex2.approx.f32 %0, %1;" : "=f"(e) : "f"(zs[j]));          \
            asm("rcp.approx.f32 %0, %1;" : "=f"(r[j]) : "f"(e + 1.0f));    \
        }                                                                  \
    } while (0)

#define CHUNK_FWD(R)                                               \
        STEP(R[0].x, R[0].y, R[0].z, R[0].w, R[1].x);              \
        STEP(R[1].y, R[1].z, R[1].w, R[2].x, R[2].y);              \
        STEP(R[2].z, R[2].w, R[3].x, R[3].y, R[3].z);              \
        STEP(R[3].w, R[4].x, R[4].y, R[4].z, R[4].w);

#define CHUNK_BWD(R)                                               \
        STEP(R[3].w, R[4].x, R[4].y, R[4].z, R[4].w);              \
        STEP(R[2].z, R[2].w, R[3].x, R[3].y, R[3].z);              \
        STEP(R[1].y, R[1].z, R[1].w, R[2].x, R[2].y);              \
        STEP(R[0].x, R[0].y, R[0].z, R[0].w, R[1].x);

    float4 A[5], B[5];
    LOADCHUNK(0, A);
    const int NCHUNK = TLEN / 4;   // 512 (even)
    if (dir == 0) {
        for (int c = 0; c < NCHUNK; c += 2) {
            LOADCHUNK(c + 1, B);
            CHUNK_FWD(A);
            if (c + 2 < NCHUNK) LOADCHUNK(c + 2, A);
            CHUNK_FWD(B);
        }
    } else {
        for (int c = 0; c < NCHUNK; c += 2) {
            LOADCHUNK(c + 1, B);
            CHUNK_BWD(A);
            if (c + 2 < NCHUNK) LOADCHUNK(c + 2, A);
            CHUNK_BWD(B);
        }
    }

    float* yo = g_y + b * (2 * H1) + dir * H1;
#pragma unroll
    for (int j = 0; j < H1; j++) yo[j] = fmaf(-2.0f, r[j], 1.0f);
#undef LOADCHUNK
#undef STEP
#undef CHUNK_FWD
#undef CHUNK_BWD
}

// ---------------------------------------------------------------------------
// Stage 2: 25-step RNN (input only at t=0) + linear 32->3.  (Proven code.)
// One warp per batch row; lane j owns neuron j. State r exchanged via
// double-buffered smem; lanes 0-2 each own one output channel.
// ---------------------------------------------------------------------------
__global__ __launch_bounds__(256) void rnn2_kernel(
    const float* __restrict__ w_ih2, const float* __restrict__ w_hh2,
    const float* __restrict__ b_ih2, const float* __restrict__ b_hh2,
    const float* __restrict__ w_out, const float* __restrict__ b_out,
    float* __restrict__ out)
{
    __shared__ __align__(16) float rbuf[8][2][H2];   // [warp][parity][32]

    const int gtid = blockIdx.x * blockDim.x + threadIdx.x;
    const int b  = gtid >> 5;
    const int j  = gtid & 31;
    const int wl = (threadIdx.x >> 5);

    float wh2[H2];
    float wsum = 0.0f;
    {
        const float4* wrow = reinterpret_cast<const float4*>(w_hh2 + j * H2);
#pragma unroll
        for (int q = 0; q < H2 / 4; q++) {
            const float4 v = __ldg(wrow + q);
            wsum += (v.x + v.y) + (v.z + v.w);
            wh2[4 * q + 0] = -2.0f * C2L2E * v.x;
            wh2[4 * q + 1] = -2.0f * C2L2E * v.y;
            wh2[4 * q + 2] = -2.0f * C2L2E * v.z;
            wh2[4 * q + 3] = -2.0f * C2L2E * v.w;
        }
    }
    const float bin = C2L2E * (__ldg(b_ih2 + j) + __ldg(b_hh2 + j));
    const float bz  = bin + C2L2E * wsum;

    const int oc = (j < 3) ? j : 0;
    float wor[H2];
    float osum = 0.0f;
    {
        const float4* orow = reinterpret_cast<const float4*>(w_out + oc * H2);
#pragma unroll
        for (int q = 0; q < H2 / 4; q++) {
            const float4 v = __ldg(orow + q);
            osum += (v.x + v.y) + (v.z + v.w);
            wor[4 * q + 0] = -2.0f * v.x;
            wor[4 * q + 1] = -2.0f * v.y;
            wor[4 * q + 2] = -2.0f * v.z;
            wor[4 * q + 3] = -2.0f * v.w;
        }
    }
    const float oconst = osum + __ldg(b_out + oc);

    float* sb = &rbuf[wl][0][0];                 // parity stride = 32 floats

    // ---- Step 0: h = tanh(W_ih2 @ y + b). Broadcast y via smem.
    sb[j] = (j < 2 * H1) ? g_y[b * (2 * H1) + j] : 0.0f;
    __syncwarp();
    float r;
    {
        const float4 y0 = *reinterpret_cast<const float4*>(sb + 0);
        const float4 y1 = *reinterpret_cast<const float4*>(sb + 4);
        const float4 y2 = *reinterpret_cast<const float4*>(sb + 8);
        const float4 y3 = *reinterpret_cast<const float4*>(sb + 12);
        const float  y16 = sb[16], y17 = sb[17];
        float za = bin, zb = 0.0f;
        const float* wi = w_ih2 + j * (2 * H1);
        za = fmaf(C2L2E * __ldg(wi + 0),  y0.x, za);
        zb = fmaf(C2L2E * __ldg(wi + 1),  y0.y, zb);
        za = fmaf(C2L2E * __ldg(wi + 2),  y0.z, za);
        zb = fmaf(C2L2E * __ldg(wi + 3),  y0.w, zb);
        za = fmaf(C2L2E * __ldg(wi + 4),  y1.x, za);
        zb = fmaf(C2L2E * __ldg(wi + 5),  y1.y, zb);
        za = fmaf(C2L2E * __ldg(wi + 6),  y1.z, za);
        zb = fmaf(C2L2E * __ldg(wi + 7),  y1.w, zb);
        za = fmaf(C2L2E * __ldg(wi + 8),  y2.x, za);
        zb = fmaf(C2L2E * __ldg(wi + 9),  y2.y, zb);
        za = fmaf(C2L2E * __ldg(wi + 10), y2.z, za);
        zb = fmaf(C2L2E * __ldg(wi + 11), y2.w, zb);
        za = fmaf(C2L2E * __ldg(wi + 12), y3.x, za);
        zb = fmaf(C2L2E * __ldg(wi + 13), y3.y, zb);
        za = fmaf(C2L2E * __ldg(wi + 14), y3.z, za);
        zb = fmaf(C2L2E * __ldg(wi + 15), y3.w, zb);
        za = fmaf(C2L2E * __ldg(wi + 16), y16, za);
        zb = fmaf(C2L2E * __ldg(wi + 17), y17, zb);
        float e;
        asm("ex2.approx.f32 %0, %1;" : "=f"(e) : "f"(za + zb));
        asm("rcp.approx.f32 %0, %1;" : "=f"(r) : "f"(e + 1.0f));
    }

    float* ob = out + (size_t)b * OUTL * 3;
    int p = 0;

    for (int t = 0; t < OUTL; t++) {
        sb[p * H2 + j] = r;
        __syncwarp();
        float rv[H2];
#pragma unroll
        for (int q = 0; q < H2; q += 4) {
            const float4 v = *reinterpret_cast<const float4*>(sb + p * H2 + q);
            rv[q] = v.x; rv[q + 1] = v.y; rv[q + 2] = v.z; rv[q + 3] = v.w;
        }

        float s0 = oconst, s1 = 0.f, s2 = 0.f, s3 = 0.f;
#pragma unroll
        for (int k = 0; k < H2; k += 4) {
            s0 = fmaf(wor[k],     rv[k],     s0);
            s1 = fmaf(wor[k + 1], rv[k + 1], s1);
            s2 = fmaf(wor[k + 2], rv[k + 2], s2);
            s3 = fmaf(wor[k + 3], rv[k + 3], s3);
        }
        if (j < 3) ob[t * 3 + j] = (s0 + s1) + (s2 + s3);

        if (t < OUTL - 1) {
            float q0 = bz, q1 = 0.f, q2 = 0.f, q3 = 0.f;
#pragma unroll
            for (int k = 0; k < H2; k += 4) {
                q0 = fmaf(wh2[k],     rv[k],     q0);
                q1 = fmaf(wh2[k + 1], rv[k + 1], q1);
                q2 = fmaf(wh2[k + 2], rv[k + 2], q2);
                q3 = fmaf(wh2[k + 3], rv[k + 3], q3);
            }
            float e;
            asm("ex2.approx.f32 %0, %1;" : "=f"(e) : "f"((q0 + q1) + (q2 + q3)));
            asm("rcp.approx.f32 %0, %1;" : "=f"(r) : "f"(e + 1.0f));
        }
        p ^= 1;
    }
}

extern "C" void kernel_launch(void* const* d_in, const int* in_sizes, int n_in,
                              void* d_out, int out_size)
{
    const float* x      = (const float*)d_in[0];
    const float* w_ih_f = (const float*)d_in[1];
    const float* w_hh_f = (const float*)d_in[2];
    const float* b_ih_f = (const float*)d_in[3];
    const float* b_hh_f = (const float*)d_in[4];
    const float* w_ih_b = (const float*)d_in[5];
    const float* w_hh_b = (const float*)d_in[6];
    const float* b_ih_b = (const float*)d_in[7];
    const float* b_hh_b = (const float*)d_in[8];
    const float* w_ih2  = (const float*)d_in[9];
    const float* w_hh2  = (const float*)d_in[10];
    const float* b_ih2  = (const float*)d_in[11];
    const float* b_hh2  = (const float*)d_in[12];
    const float* w_out  = (const float*)d_in[13];
    const float* b_out  = (const float*)d_in[14];
    float* out = (float*)d_out;

    // Stage 1: thread per sequence. 8192 threads = 64 blocks x 128.
    rnn1_kernel<<<(2 * BATCH) / 128, 128>>>(x, w_ih_f, w_hh_f, b_ih_f, b_hh_f,
                                            w_ih_b, w_hh_b, b_ih_b, b_hh_b);

    // Stage 2: warp per batch row.
    rnn2_kernel<<<(BATCH * 32) / 256, 256>>>(w_ih2, w_hh2, b_ih2, b_hh2,
                                             w_out, b_out, out);
}

// round 16
// speedup vs baseline: 1.6630x; 1.1835x over previous
#include <cuda_runtime.h>
#include <cuda_bf16.h>

#define BATCH 4096
#define TLEN  2048
#define DIN   5
#define H1    9
#define H2    32
#define OUTL  25

// 2*log2(e): folded into stage-1/2 weights so tanh needs no pre-multiply.
#define C2L2E 2.8853900817779268f

#define MASK27 0x07FFFFFFu
#define NW1    2732          // stage-1 warps: 1366 per direction, 3 seqs each

// Scratch for stage-1 result y = [h_f | h_b] per batch row.
__device__ float g_y[BATCH * 2 * H1];

// ---------------------------------------------------------------------------
// Stage 1: bidirectional Elman RNN, T=2048. Lane-per-neuron, 3 groups of 9
// lanes (3 seqs/warp, 2732 warps = 4.6/SMSP). State r = rcp(exp(z')+1)
// exchanged via double-buffered smem. h = 1-2r folded into weights/bias.
// CRITICAL-PATH version: the input part zin(t+1) = bz + wih*x(t+1) is
// computed per-lane in the STS->syncwarp drain window, so the loop-carried
// path is only STS -> sync -> LDS -> 5-deep whh chain -> ex2 -> rcp.
// ---------------------------------------------------------------------------
__global__ __launch_bounds__(128) void rnn1_kernel(
    const float* __restrict__ x,
    const float* __restrict__ w_ih_f, const float* __restrict__ w_hh_f,
    const float* __restrict__ b_ih_f, const float* __restrict__ b_hh_f,
    const float* __restrict__ w_ih_b, const float* __restrict__ w_hh_b,
    const float* __restrict__ b_ih_b, const float* __restrict__ b_hh_b)
{
    __shared__ __align__(16) float hx[4][2][3][12];  // [warp][parity][group][12]

    const int lane = threadIdx.x & 31;
    if (lane >= 27) return;                       // 3 groups of 9 lanes
    const int wl   = threadIdx.x >> 5;
    const int warp = blockIdx.x * 4 + wl;
    if (warp >= NW1) return;

    const int g  = lane / 9;
    const int j  = lane - 9 * g;
    const int dir = (warp >= NW1 / 2) ? 1 : 0;       // 1366 warps per dir
    const int wd  = warp - dir * (NW1 / 2);
    const int sr  = wd * 3 + g;                      // raw sequence id
    const int b   = (sr < BATCH) ? sr : (BATCH - 1);
    const bool store_ok = (sr < BATCH);

    const float* wih_g = dir ? w_ih_b : w_ih_f;
    const float* whh_g = dir ? w_hh_b : w_hh_f;
    const float* bi_g  = dir ? b_ih_b : b_ih_f;
    const float* bh_g  = dir ? b_hh_b : b_hh_f;

    float wih[DIN], whh2[H1];
    float wsum = 0.0f;
#pragma unroll
    for (int d = 0; d < DIN; d++) wih[d] = C2L2E * __ldg(wih_g + j * DIN + d);
#pragma unroll
    for (int k = 0; k < H1; k++) {
        float w = __ldg(whh_g + j * H1 + k);
        wsum += w;
        whh2[k] = -2.0f * C2L2E * w;
    }
    const float bz2 = C2L2E * (__ldg(bi_g + j) + __ldg(bh_g + j) + wsum);
    float r   = 0.5f;                             // h = 1-2r = 0
    float zin = 0.0f;                             // input part of current step

    float* sbase = &hx[wl][0][g][0];              // parity stride = 36 floats

    const float4* xq = reinterpret_cast<const float4*>(x + (size_t)b * (TLEN * DIN));
    const int q0  = dir ? (TLEN / 4 - 1) * DIN : 0;   // 2555 or 0
    const int qdq = dir ? -DIN : DIN;

#define LOADCHUNK(c, R) do {                                   \
        const float4* _p = xq + (q0 + (c) * qdq);              \
        R[0] = __ldg(_p + 0); R[1] = __ldg(_p + 1);            \
        R[2] = __ldg(_p + 2); R[3] = __ldg(_p + 3);            \
        R[4] = __ldg(_p + 4);                                  \
    } while (0)

    // zin for one step (off the serial path): bz + sum_d wih[d]*x_d
#define ZIN(dst, x0, x1, x2, x3, x4) do {                                  \
        float t_ = fmaf(wih[0], (x0), bz2);                                \
        t_ = fmaf(wih[1], (x1), t_);                                       \
        t_ = fmaf(wih[2], (x2), t_);                                       \
        t_ = fmaf(wih[3], (x3), t_);                                       \
        dst = fmaf(wih[4], (x4), t_);                                      \
    } while (0)

    // One step. On entry r and zin are for step t; the x args are step t+1's
    // input (consumed in the STS-drain window to build the next zin).
#define STEP(P, x0, x1, x2, x3, x4) do {                                   \
        sbase[(P) * 36 + j] = r;                                           \
        float nzin;                                                        \
        ZIN(nzin, x0, x1, x2, x3, x4);                                     \
        __syncwarp(MASK27);                                                \
        const float4 ra = *reinterpret_cast<const float4*>(sbase + (P) * 36);     \
        const float4 rb = *reinterpret_cast<const float4*>(sbase + (P) * 36 + 4); \
        const float  r8 = sbase[(P) * 36 + 8];                             \
        float za = fmaf(whh2[0], ra.x, zin);                               \
        float zb = whh2[1] * ra.y;                                         \
        za = fmaf(whh2[2], ra.z, za);                                      \
        zb = fmaf(whh2[3], ra.w, zb);                                      \
        za = fmaf(whh2[4], rb.x, za);                                      \
        zb = fmaf(whh2[5], rb.y, zb);                                      \
        za = fmaf(whh2[6], rb.z, za);                                      \
        zb = fmaf(whh2[7], rb.w, zb);                                      \
        za = fmaf(whh2[8], r8, za);                                        \
        float e;                                                           \
        asm("ex2.approx.f32 %0, %1;" : "=f"(e) : "f"(za + zb));            \
        asm("rcp.approx.f32 %0, %1;" : "=f"(r) : "f"(e + 1.0f));           \
        zin = nzin;                                                        \
    } while (0)

    // Chunk = 4 steps; step t of a chunk uses floats [5t..5t+4]. Each STEP
    // passes the NEXT step's x; the chunk's last STEP needs the next chunk's
    // first-step x (RN).
#define CHUNK_FWD(R, RN)                                                   \
        STEP(0, R[1].y, R[1].z, R[1].w, R[2].x, R[2].y);                   \
        STEP(1, R[2].z, R[2].w, R[3].x, R[3].y, R[3].z);                   \
        STEP(0, R[3].w, R[4].x, R[4].y, R[4].z, R[4].w);                   \
        STEP(1, RN[0].x, RN[0].y, RN[0].z, RN[0].w, RN[1].x);

#define CHUNK_BWD(R, RN)                                                   \
        STEP(0, R[2].z, R[2].w, R[3].x, R[3].y, R[3].z);                   \
        STEP(1, R[1].y, R[1].z, R[1].w, R[2].x, R[2].y);                   \
        STEP(0, R[0].x, R[0].y, R[0].z, R[0].w, R[1].x);                   \
        STEP(1, RN[3].w, RN[4].x, RN[4].y, RN[4].z, RN[4].w);

    float4 A[5], B[5];
    LOADCHUNK(0, A);
    // Prime zin with the true first step's input part.
    if (dir == 0) ZIN(zin, A[0].x, A[0].y, A[0].z, A[0].w, A[1].x);
    else          ZIN(zin, A[3].w, A[4].x, A[4].y, A[4].z, A[4].w);

    const int NCHUNK = TLEN / 4;   // 512 (even)
    if (dir == 0) {
        for (int c = 0; c < NCHUNK; c += 2) {
            LOADCHUNK(c + 1, B);
            CHUNK_FWD(A, B);
            if (c + 2 < NCHUNK) LOADCHUNK(c + 2, A);
            CHUNK_FWD(B, A);   // final iter: nzin from stale A is for step
                               // 2048 and never consumed
        }
    } else {
        for (int c = 0; c < NCHUNK; c += 2) {
            LOADCHUNK(c + 1, B);
            CHUNK_BWD(A, B);
            if (c + 2 < NCHUNK) LOADCHUNK(c + 2, A);
            CHUNK_BWD(B, A);
        }
    }

    if (store_ok)
        g_y[b * (2 * H1) + dir * H1 + j] = fmaf(-2.0f, r, 1.0f);
#undef LOADCHUNK
#undef ZIN
#undef STEP
#undef CHUNK_FWD
#undef CHUNK_BWD
}

// ---------------------------------------------------------------------------
// Stage 2: 25-step RNN (input only at t=0) + linear 32->3.  (Proven R13 code,
// measured 27.9 us.)
// ---------------------------------------------------------------------------
__global__ __launch_bounds__(256) void rnn2_kernel(
    const float* __restrict__ w_ih2, const float* __restrict__ w_hh2,
    const float* __restrict__ b_ih2, const float* __restrict__ b_hh2,
    const float* __restrict__ w_out, const float* __restrict__ b_out,
    float* __restrict__ out)
{
    __shared__ __align__(16) float rbuf[8][2][H2];   // [warp][parity][32]

    const int gtid = blockIdx.x * blockDim.x + threadIdx.x;
    const int b  = gtid >> 5;
    const int j  = gtid & 31;
    const int wl = (threadIdx.x >> 5);

    float wh2[H2];
    float wsum = 0.0f;
    {
        const float4* wrow = reinterpret_cast<const float4*>(w_hh2 + j * H2);
#pragma unroll
        for (int q = 0; q < H2 / 4; q++) {
            const float4 v = __ldg(wrow + q);
            wsum += (v.x + v.y) + (v.z + v.w);
            wh2[4 * q + 0] = -2.0f * C2L2E * v.x;
            wh2[4 * q + 1] = -2.0f * C2L2E * v.y;
            wh2[4 * q + 2] = -2.0f * C2L2E * v.z;
            wh2[4 * q + 3] = -2.0f * C2L2E * v.w;
        }
    }
    const float bin = C2L2E * (__ldg(b_ih2 + j) + __ldg(b_hh2 + j));
    const float bz  = bin + C2L2E * wsum;

    const int oc = (j < 3) ? j : 0;
    float wor[H2];
    float osum = 0.0f;
    {
        const float4* orow = reinterpret_cast<const float4*>(w_out + oc * H2);
#pragma unroll
        for (int q = 0; q < H2 / 4; q++) {
            const float4 v = __ldg(orow + q);
            osum += (v.x + v.y) + (v.z + v.w);
            wor[4 * q + 0] = -2.0f * v.x;
            wor[4 * q + 1] = -2.0f * v.y;
            wor[4 * q + 2] = -2.0f * v.z;
            wor[4 * q + 3] = -2.0f * v.w;
        }
    }
    const float oconst = osum + __ldg(b_out + oc);

    float* sb = &rbuf[wl][0][0];                 // parity stride = 32 floats

    // ---- Step 0: h = tanh(W_ih2 @ y + b). Broadcast y via smem.
    sb[j] = (j < 2 * H1) ? g_y[b * (2 * H1) + j] : 0.0f;
    __syncwarp();
    float r;
    {
        const float4 y0 = *reinterpret_cast<const float4*>(sb + 0);
        const float4 y1 = *reinterpret_cast<const float4*>(sb + 4);
        const float4 y2 = *reinterpret_cast<const float4*>(sb + 8);
        const float4 y3 = *reinterpret_cast<const float4*>(sb + 12);
        const float  y16 = sb[16], y17 = sb[17];
        float za = bin, zb = 0.0f;
        const float* wi = w_ih2 + j * (2 * H1);
        za = fmaf(C2L2E * __ldg(wi + 0),  y0.x, za);
        zb = fmaf(C2L2E * __ldg(wi + 1),  y0.y, zb);
        za = fmaf(C2L2E * __ldg(wi + 2),  y0.z, za);
        zb = fmaf(C2L2E * __ldg(wi + 3),  y0.w, zb);
        za = fmaf(C2L2E * __ldg(wi + 4),  y1.x, za);
        zb = fmaf(C2L2E * __ldg(wi + 5),  y1.y, zb);
        za = fmaf(C2L2E * __ldg(wi + 6),  y1.z, za);
        zb = fmaf(C2L2E * __ldg(wi + 7),  y1.w, zb);
        za = fmaf(C2L2E * __ldg(wi + 8),  y2.x, za);
        zb = fmaf(C2L2E * __ldg(wi + 9),  y2.y, zb);
        za = fmaf(C2L2E * __ldg(wi + 10), y2.z, za);
        zb = fmaf(C2L2E * __ldg(wi + 11), y2.w, zb);
        za = fmaf(C2L2E * __ldg(wi + 12), y3.x, za);
        zb = fmaf(C2L2E * __ldg(wi + 13), y3.y, zb);
        za = fmaf(C2L2E * __ldg(wi + 14), y3.z, za);
        zb = fmaf(C2L2E * __ldg(wi + 15), y3.w, zb);
        za = fmaf(C2L2E * __ldg(wi + 16), y16, za);
        zb = fmaf(C2L2E * __ldg(wi + 17), y17, zb);
        float e;
        asm("ex2.approx.f32 %0, %1;" : "=f"(e) : "f"(za + zb));
        asm("rcp.approx.f32 %0, %1;" : "=f"(r) : "f"(e + 1.0f));
    }

    float* ob = out + (size_t)b * OUTL * 3;
    int p = 0;

    for (int t = 0; t < OUTL; t++) {
        sb[p * H2 + j] = r;
        __syncwarp();
        float rv[H2];
#pragma unroll
        for (int q = 0; q < H2; q += 4) {
            const float4 v = *reinterpret_cast<const float4*>(sb + p * H2 + q);
            rv[q] = v.x; rv[q + 1] = v.y; rv[q + 2] = v.z; rv[q + 3] = v.w;
        }

        float s0 = oconst, s1 = 0.f, s2 = 0.f, s3 = 0.f;
#pragma unroll
        for (int k = 0; k < H2; k += 4) {
            s0 = fmaf(wor[k],     rv[k],     s0);
            s1 = fmaf(wor[k + 1], rv[k + 1], s1);
            s2 = fmaf(wor[k + 2], rv[k + 2], s2);
            s3 = fmaf(wor[k + 3], rv[k + 3], s3);
        }
        if (j < 3) ob[t * 3 + j] = (s0 + s1) + (s2 + s3);

        if (t < OUTL - 1) {
            float q0 = bz, q1 = 0.f, q2 = 0.f, q3 = 0.f;
#pragma unroll
            for (int k = 0; k < H2; k += 4) {
                q0 = fmaf(wh2[k],     rv[k],     q0);
                q1 = fmaf(wh2[k + 1], rv[k + 1], q1);
                q2 = fmaf(wh2[k + 2], rv[k + 2], q2);
                q3 = fmaf(wh2[k + 3], rv[k + 3], q3);
            }
            float e;
            asm("ex2.approx.f32 %0, %1;" : "=f"(e) : "f"((q0 + q1) + (q2 + q3)));
            asm("rcp.approx.f32 %0, %1;" : "=f"(r) : "f"(e + 1.0f));
        }
        p ^= 1;
    }
}

extern "C" void kernel_launch(void* const* d_in, const int* in_sizes, int n_in,
                              void* d_out, int out_size)
{
    const float* x      = (const float*)d_in[0];
    const float* w_ih_f = (const float*)d_in[1];
    const float* w_hh_f = (const float*)d_in[2];
    const float* b_ih_f = (const float*)d_in[3];
    const float* b_hh_f = (const float*)d_in[4];
    const float* w_ih_b = (const float*)d_in[5];
    const float* w_hh_b = (const float*)d_in[6];
    const float* b_ih_b = (const float*)d_in[7];
    const float* b_hh_b = (const float*)d_in[8];
    const float* w_ih2  = (const float*)d_in[9];
    const float* w_hh2  = (const float*)d_in[10];
    const float* b_ih2  = (const float*)d_in[11];
    const float* b_hh2  = (const float*)d_in[12];
    const float* w_out  = (const float*)d_in[13];
    const float* b_out  = (const float*)d_in[14];
    float* out = (float*)d_out;

    // Stage 1: 2732 warps (1366 per direction, 3 seqs each), 4 warps/block.
    rnn1_kernel<<<(NW1 + 3) / 4, 128>>>(x, w_ih_f, w_hh_f, b_ih_f, b_hh_f,
                                        w_ih_b, w_hh_b, b_ih_b, b_hh_b);

    // Stage 2: warp per batch row.
    rnn2_kernel<<<(BATCH * 32) / 256, 256>>>(w_ih2, w_hh2, b_ih2, b_hh2,
                                             w_out, b_out, out);
}